// round 15
// baseline (speedup 1.0000x reference)
#include <cuda_runtime.h>
#include <cuda_bf16.h>
#include <cstdint>

// RochetNet forward — two-phase, both phases hardware-proven:
//   Phase A (round 9, passed): single-pass bf16 HMMA on all rows; finalize
//     rows with top-2 gap > 0.04 and |max| > 0.02:
//       alloc = clip(W[idx]) (= W[idx], W in [0,1)),
//       pay   = relu(-w0[idx]) if max>0 else 0
//       (identity: sum(alloc*v) = hidden[idx] - w0[idx]).
//     ~8-11% of rows deferred to the queue.
//   Phase B (round 11, passed): exact serial-order fp32 rescore from
//     smem-staged W [256][65] (conflict-free), matching the reference's
//     accumulation order bit-for-bit on the deferred rows.
// Output: alloc [B*64] floats, then payments [B].

#define ITEMS   64
#define HIDDEN  256
#define TILE_M  128
#define BMAX    1000000
#define GAP_A   0.04f
#define SGN_A   0.02f

__device__ int g_tie_count;
__device__ int g_tie_rows[BMAX];

__global__ void zero_count_kernel() { g_tie_count = 0; }

// ---------------------------------------------------------------- helpers ---
__device__ __forceinline__ uint32_t smem_u32(const void* p) {
    uint32_t a;
    asm("{ .reg .u64 t; cvta.to.shared.u64 t, %1; cvt.u32.u64 %0, t; }"
        : "=r"(a) : "l"(p));
    return a;
}
#define CVT_BF16X2_F32(res, a, b) \
    asm("cvt.rn.satfinite.bf16x2.f32 %0, %1, %2;" : "=r"(res) : "f"(b), "f"(a))
#define LDSM_X4(r0, r1, r2, r3, addr) \
    asm volatile("ldmatrix.sync.aligned.m8n8.x4.shared.b16 {%0,%1,%2,%3}, [%4];" \
                 : "=r"(r0), "=r"(r1), "=r"(r2), "=r"(r3) : "r"(addr))
#define MMA_16816(d0, d1, d2, d3, a0, a1, a2, a3, b0, b1) \
    asm volatile("mma.sync.aligned.m16n8k16.row.col.f32.bf16.bf16.f32 " \
                 "{%0,%1,%2,%3}, {%4,%5,%6,%7}, {%8,%9}, {%0,%1,%2,%3};" \
                 : "+f"(d0), "+f"(d1), "+f"(d2), "+f"(d3) \
                 : "r"(a0), "r"(a1), "r"(a2), "r"(a3), "r"(b0), "r"(b1))

#define WROW_B 144

// =================================================================== Phase A
// smem: W bf16 [256][144B], V bf16 8 warps x [16][144B], w0, stage
#define A_WB    0
#define A_VB    (A_WB + HIDDEN * WROW_B)               // 36864
#define A_W0    (A_VB + 8 * 16 * WROW_B)               // 55296
#define A_SIDX  (A_W0 + HIDDEN * 4)                    // 56320
#define A_SPAY  (A_SIDX + 8 * 16 * 4)                  // 56832
#define A_TOTAL (A_SPAY + 8 * 16 * 4)                  // 57344

__global__ void __launch_bounds__(256, 2)
rochet_tierA_kernel(const float* __restrict__ V,
                    const float* __restrict__ W,
                    const float* __restrict__ w0,
                    float* __restrict__ alloc_out,
                    float* __restrict__ pay_out,
                    int B) {
    extern __shared__ char smem[];
    const int tid  = threadIdx.x;
    const int wid  = tid >> 5;
    const int lane = tid & 31;

    float* w0s  = (float*)(smem + A_W0);
    int*   sIdx = (int*)(smem + A_SIDX);
    float* sPay = (float*)(smem + A_SPAY);

    for (int i = tid; i < HIDDEN * ITEMS / 4; i += 256) {
        float4 f = __ldg((const float4*)W + i);
        int row = i >> 4, c4 = i & 15;
        uint32_t b0, b1;
        CVT_BF16X2_F32(b0, f.x, f.y);
        CVT_BF16X2_F32(b1, f.z, f.w);
        *(uint2*)(smem + A_WB + row * WROW_B + c4 * 8) = make_uint2(b0, b1);
    }
    if (tid < HIDDEN) w0s[tid] = __ldg(w0 + tid);
    __syncthreads();

    const int base = blockIdx.x * TILE_M + wid * 16;

    char* vb = smem + A_VB + wid * 16 * WROW_B;
    #pragma unroll
    for (int it = 0; it < 8; it++) {
        int idx = it * 32 + lane;
        int row = idx >> 4, c4 = idx & 15;
        int grow = base + row;
        float4 f = (grow < B)
            ? __ldg((const float4*)(V + (size_t)grow * ITEMS) + c4)
            : make_float4(0.f, 0.f, 0.f, 0.f);
        uint32_t b0, b1;
        CVT_BF16X2_F32(b0, f.x, f.y);
        CVT_BF16X2_F32(b1, f.z, f.w);
        *(uint2*)(vb + row * WROW_B + c4 * 8) = make_uint2(b0, b1);
    }
    __syncwarp();

    uint32_t a[4][4];
    {
        const uint32_t arow = lane & 15;
        const uint32_t acol = (lane & 16) >> 1;
        uint32_t ab = smem_u32(vb) + arow * WROW_B + acol * 2;
        #pragma unroll
        for (int kk = 0; kk < 4; kk++)
            LDSM_X4(a[kk][0], a[kk][1], a[kk][2], a[kk][3], ab + kk * 32);
    }

    float best0 = -1e30f, sec0 = -1e30f, best1 = -1e30f, sec1 = -1e30f;
    int   idx0 = 0, idx1 = 0;
    const uint32_t brow  = lane & 7;
    const uint32_t bcol8 = ((lane >> 3) & 3) * 8;
    const uint32_t wbase = smem_u32(smem + A_WB) + brow * WROW_B + bcol8 * 2;
    const int      cbase = 2 * (lane & 3);

    #pragma unroll 4
    for (int nt = 0; nt < 32; nt++) {
        uint32_t b[8];
        uint32_t ad = wbase + (uint32_t)nt * 8 * WROW_B;
        LDSM_X4(b[0], b[1], b[2], b[3], ad);
        LDSM_X4(b[4], b[5], b[6], b[7], ad + 64);
        float d0 = 0.f, d1 = 0.f, d2 = 0.f, d3 = 0.f;
        MMA_16816(d0, d1, d2, d3, a[0][0], a[0][1], a[0][2], a[0][3], b[0], b[1]);
        MMA_16816(d0, d1, d2, d3, a[1][0], a[1][1], a[1][2], a[1][3], b[2], b[3]);
        MMA_16816(d0, d1, d2, d3, a[2][0], a[2][1], a[2][2], a[2][3], b[4], b[5]);
        MMA_16816(d0, d1, d2, d3, a[3][0], a[3][1], a[3][2], a[3][3], b[6], b[7]);

        const int  col = nt * 8 + cbase;
        float2 wv = *(const float2*)(w0s + col);
        float h;
        h = d0 + wv.x;
        if (h > best0) { sec0 = best0; best0 = h; idx0 = col; }
        else if (h > sec0) sec0 = h;
        h = d1 + wv.y;
        if (h > best0) { sec0 = best0; best0 = h; idx0 = col + 1; }
        else if (h > sec0) sec0 = h;
        h = d2 + wv.x;
        if (h > best1) { sec1 = best1; best1 = h; idx1 = col; }
        else if (h > sec1) sec1 = h;
        h = d3 + wv.y;
        if (h > best1) { sec1 = best1; best1 = h; idx1 = col + 1; }
        else if (h > sec1) sec1 = h;
    }

    #pragma unroll
    for (int off = 1; off <= 2; off <<= 1) {
        float ob, os; int oi;
        ob = __shfl_xor_sync(0xffffffffu, best0, off);
        os = __shfl_xor_sync(0xffffffffu, sec0,  off);
        oi = __shfl_xor_sync(0xffffffffu, idx0,  off);
        sec0 = fmaxf(fmaxf(sec0, os), fminf(best0, ob));
        if (ob > best0 || (ob == best0 && oi < idx0)) { best0 = ob; idx0 = oi; }
        ob = __shfl_xor_sync(0xffffffffu, best1, off);
        os = __shfl_xor_sync(0xffffffffu, sec1,  off);
        oi = __shfl_xor_sync(0xffffffffu, idx1,  off);
        sec1 = fmaxf(fmaxf(sec1, os), fminf(best1, ob));
        if (ob > best1 || (ob == best1 && oi < idx1)) { best1 = ob; idx1 = oi; }
    }

    if ((lane & 3) == 0) {
        const int q = lane >> 2;
        #pragma unroll
        for (int half = 0; half < 2; half++) {
            const int   r    = q + half * 8;
            const float b    = half ? best1 : best0;
            const float s    = half ? sec1  : sec0;
            const int   bi   = half ? idx1  : idx0;
            const int   grow = base + r;
            int enc = -1;
            float pay = 0.f;
            if (grow < B) {
                if ((b - s <= GAP_A) || (fabsf(b) <= SGN_A)) {
                    int slot = atomicAdd(&g_tie_count, 1);
                    g_tie_rows[slot] = grow;
                } else {
                    const int win = (b > 0.f) ? 1 : 0;
                    enc = bi | (win << 16);
                    pay = win ? fmaxf(-w0s[bi], 0.f) : 0.f;
                }
            }
            sIdx[wid * 16 + r] = enc;
            sPay[wid * 16 + r] = pay;
        }
    }
    __syncwarp();

    #pragma unroll 1
    for (int r = 0; r < 16; r++) {
        const int enc = sIdx[wid * 16 + r];
        if (enc < 0) continue;
        const int grow = base + r;
        const int win  = enc >> 16;
        const int bi   = enc & 0xffff;
        float2 t = make_float2(0.f, 0.f);
        if (win) {
            t = __ldg((const float2*)(W + (size_t)bi * ITEMS) + lane);
            t.x = fminf(fmaxf(t.x, 0.f), 1.f);
            t.y = fminf(fmaxf(t.y, 0.f), 1.f);
        }
        ((float2*)(alloc_out + (size_t)grow * ITEMS))[lane] = t;
        if (lane == 0) pay_out[grow] = sPay[wid * 16 + r];
    }
}

// =================================================================== Phase B
// Exact serial-order fp32 rescore from smem-staged W [256][65] (queue).
#define BROW 65
#define C_TOTAL (HIDDEN * BROW * 4 + HIDDEN * 4)

__global__ void __launch_bounds__(256)
rochet_rescue_kernel(const float* __restrict__ V,
                     const float* __restrict__ W,
                     const float* __restrict__ w0,
                     float* __restrict__ alloc_out,
                     float* __restrict__ pay_out) {
    extern __shared__ float shb[];
    float* Ws  = shb;                       // [256][65]
    float* w0s = shb + HIDDEN * BROW;

    const int tid  = threadIdx.x;
    const int lane = tid & 31;

    for (int i = tid; i < HIDDEN * ITEMS; i += 256) {
        int row = i >> 6, col = i & 63;
        Ws[row * BROW + col] = __ldg(W + i);
    }
    if (tid < HIDDEN) w0s[tid] = __ldg(w0 + tid);
    __syncthreads();

    const int warp_global = (blockIdx.x * blockDim.x + tid) >> 5;
    const int nwarps      = (gridDim.x * blockDim.x) >> 5;
    const int cnt         = g_tie_count;

    for (int q = warp_global; q < cnt; q += nwarps) {
        const int row = g_tie_rows[q];
        const float* v = V + (size_t)row * ITEMS;

        float vr[ITEMS];
        #pragma unroll
        for (int i = 0; i < ITEMS / 4; i++) {
            float4 t = reinterpret_cast<const float4*>(v)[i];
            vr[4 * i + 0] = t.x; vr[4 * i + 1] = t.y;
            vr[4 * i + 2] = t.z; vr[4 * i + 3] = t.w;
        }

        float best = -1e30f;
        int   bidx = HIDDEN;
        #pragma unroll 1
        for (int jj = 0; jj < HIDDEN / 32; jj++) {
            const int j = jj * 32 + lane;
            const float* wr = Ws + j * BROW;
            float acc = 0.0f;
            #pragma unroll
            for (int i = 0; i < ITEMS; i++)
                acc = fmaf(vr[i], wr[i], acc);           // strict serial order
            float h = acc + w0s[j];                      // single bias rounding
            if (h > best || (h == best && j < bidx)) { best = h; bidx = j; }
        }
        #pragma unroll
        for (int off = 16; off; off >>= 1) {
            float ov = __shfl_down_sync(0xffffffffu, best, off);
            int   oi = __shfl_down_sync(0xffffffffu, bidx, off);
            if (ov > best || (ov == best && oi < bidx)) { best = ov; bidx = oi; }
        }
        best = __shfl_sync(0xffffffffu, best, 0);
        bidx = __shfl_sync(0xffffffffu, bidx, 0);

        const bool win = (best > 0.0f);
        float2 t = make_float2(0.f, 0.f);
        if (win) {
            t = __ldg((const float2*)(W + (size_t)bidx * ITEMS) + lane);
            t.x = fminf(fmaxf(t.x, 0.0f), 1.0f);
            t.y = fminf(fmaxf(t.y, 0.0f), 1.0f);
        }
        ((float2*)(alloc_out + (size_t)row * ITEMS))[lane] = t;

        float pd = fmaf(t.y, vr[2 * lane + 1], t.x * vr[2 * lane]);
        #pragma unroll
        for (int off = 16; off; off >>= 1)
            pd += __shfl_down_sync(0xffffffffu, pd, off);
        if (lane == 0)
            pay_out[row] = fmaxf(pd - fmaxf(best, 0.0f), 0.0f);
    }
}

extern "C" void kernel_launch(void* const* d_in, const int* in_sizes, int n_in,
                              void* d_out, int out_size) {
    const float* V  = (const float*)d_in[0];   // [B, 64]
    const float* W  = (const float*)d_in[1];   // [256, 64]
    const float* w0 = (const float*)d_in[2];   // [256]

    const int B = in_sizes[0] / ITEMS;
    float* alloc_out = (float*)d_out;
    float* pay_out   = (float*)d_out + (size_t)B * ITEMS;

    const int ntiles = (B + TILE_M - 1) / TILE_M;

    // One-time setup (kept out of the graph-captured call sequence).
    static bool inited = false;
    if (!inited) {
        inited = true;
        cudaFuncSetAttribute(rochet_tierA_kernel,
                             cudaFuncAttributeMaxDynamicSharedMemorySize,
                             A_TOTAL);
        cudaFuncSetAttribute(rochet_rescue_kernel,
                             cudaFuncAttributeMaxDynamicSharedMemorySize,
                             C_TOTAL);
    }

    zero_count_kernel<<<1, 1>>>();
    rochet_tierA_kernel<<<ntiles, 256, A_TOTAL>>>(V, W, w0, alloc_out,
                                                  pay_out, B);
    rochet_rescue_kernel<<<444, 256, C_TOTAL>>>(V, W, w0, alloc_out, pay_out);
}